// round 8
// baseline (speedup 1.0000x reference)
#include <cuda_runtime.h>
#include <cstdint>

#define B_ 32
#define D_ 128
#define T_ 2250
#define Q_ 32
#define K_ 1024
#define N_ (B_*T_)          // 72000
#define PTILE 256
#define NBLK 282            // ceil(N/256)

// Residual scratch [N][D] and per-code squared norms [Q][K].
__device__ __align__(16) float g_resid[(size_t)N_ * D_];
__device__ __align__(16) float g_cnorm[Q_ * K_];

// ---------------------------------------------------------------------------
__global__ void transpose_kernel(const float* __restrict__ in)
{
    __shared__ float tile[32][33];
    const int b  = blockIdx.z;
    const int t0 = blockIdx.x * 32;
    const int d0 = blockIdx.y * 32;
    const int tx = threadIdx.x;
    const int ty = threadIdx.y;

    #pragma unroll
    for (int k = 0; k < 4; k++) {
        int d = d0 + ty + k * 8;
        int t = t0 + tx;
        float v = 0.0f;
        if (t < T_) v = in[((size_t)b * D_ + d) * T_ + t];
        tile[ty + k * 8][tx] = v;
    }
    __syncthreads();
    #pragma unroll
    for (int k = 0; k < 4; k++) {
        int t = t0 + ty + k * 8;
        int d = d0 + tx;
        if (t < T_) g_resid[((size_t)b * T_ + t) * D_ + d] = tile[tx][ty + k * 8];
    }
}

// ---------------------------------------------------------------------------
__global__ void cnorm_kernel(const float* __restrict__ embed)
{
    const int wid  = threadIdx.x >> 5;
    const int lane = threadIdx.x & 31;
    const int code = blockIdx.x * 8 + wid;
    float s = 0.0f;
    #pragma unroll
    for (int j = 0; j < 4; j++) {
        float v = embed[(size_t)code * D_ + lane + 32 * j];
        s = fmaf(v, v, s);
    }
    #pragma unroll
    for (int d = 16; d; d >>= 1) s += __shfl_xor_sync(0xffffffffu, s, d);
    if (lane == 0) g_cnorm[code] = s;
}

// ---------------------------------------------------------------------------
// Packed dual-FMA: acc.(lo,hi) += a.(lo,hi) * b.(lo,hi)   (sm_100+ f32x2)
__device__ __forceinline__ void ffma2(unsigned long long& acc,
                                      unsigned long long a,
                                      unsigned long long b)
{
    asm("fma.rn.f32x2 %0, %1, %2, %0;" : "+l"(acc) : "l"(a), "l"(b));
}

// cp.async 16B global -> shared
__device__ __forceinline__ void cp_async16(void* smem_dst, const void* gmem_src)
{
    unsigned saddr = (unsigned)__cvta_generic_to_shared(smem_dst);
    asm volatile("cp.async.cg.shared.global [%0], [%1], 16;"
                 :: "r"(saddr), "l"(gmem_src) : "memory");
}
__device__ __forceinline__ void cp_async_commit()
{
    asm volatile("cp.async.commit_group;" ::: "memory");
}
__device__ __forceinline__ void cp_async_wait_all()
{
    asm volatile("cp.async.wait_group 0;" ::: "memory");
}

// ---------------------------------------------------------------------------
// One RVQ layer. Block = 512 threads (tx = tid&7, ty = tid>>3), 256 points.
// K in 16 chunks of 64 codes (double-buffered via cp.async), D=128 in smem.
// Thread micro-tile: 4 points (p = ty + 64*jp) x 8 codes (c = tx + 8*jc).
// Per-dot arithmetic order IDENTICAL to rounds 5-7: for d4 = 0..31 ascending,
// acc += r01*e01 then acc += r23*e23; final score 2*(lo+hi) - |e|^2.
// smem: r 256x33 f4 (135KB) + e 2x64x33 f4 (67.6KB) + sidx = 203.8 KB.
// ---------------------------------------------------------------------------
#define RPAD 33
#define RT_F4 (PTILE * RPAD)    // 8448 float4
#define ET_F4 (64 * RPAD)       // 2112 float4 per buffer

__global__ void __launch_bounds__(512, 1)
rvq_layer_kernel(const float* __restrict__ embed_all, int q, float* __restrict__ out)
{
    extern __shared__ float4 sm4[];
    float4* r4s  = sm4;                            // 135,168 B
    float4* ebuf = sm4 + RT_F4;                    // 2 x 33,792 B
    int*    sidx = (int*)(sm4 + RT_F4 + 2 * ET_F4);  // 1024 B

    const int tid = threadIdx.x;
    const int tx  = tid & 7;            // code group: 8 codes (c = tx + 8*jc)
    const int ty  = tid >> 3;           // point group: 0..63 (p = ty + 64*jp)
    const int blockStart = blockIdx.x * PTILE;

    const float4* eq = (const float4*)(embed_all + (size_t)q * (K_ * D_));
    float4* rg = (float4*)g_resid;

    // ---- load residual tile: 256 pts x 32 float4 ----
    #pragma unroll
    for (int i = 0; i < 16; i++) {
        int f  = tid + 512 * i;
        int p  = f >> 5;
        int s0 = f & 31;
        int n  = blockStart + p;
        if (n >= N_) n = 0;
        r4s[p * RPAD + s0] = rg[(size_t)n * 32 + s0];
    }

    // ---- prefetch e chunk 0 into buffer 0 via cp.async ----
    #pragma unroll
    for (int i = 0; i < 4; i++) {
        int f   = tid + 512 * i;
        int row = f >> 5;               // 0..63
        int s0  = f & 31;
        cp_async16(&ebuf[row * RPAD + s0], &eq[(size_t)row * 32 + s0]);
    }
    cp_async_commit();

    float best[4];
    int   bidx[4];
    #pragma unroll
    for (int j = 0; j < 4; j++) { best[j] = -3.4e38f; bidx[j] = 0; }

    for (int ch = 0; ch < 16; ++ch) {
        const float4* eb = ebuf + (ch & 1) * ET_F4;
        cp_async_wait_all();
        __syncthreads();   // buffer (ch&1) filled; previous readers done

        // ---- prefetch next chunk into the other buffer ----
        if (ch < 15) {
            float4* en = ebuf + ((ch + 1) & 1) * ET_F4;
            #pragma unroll
            for (int i = 0; i < 4; i++) {
                int f   = tid + 512 * i;
                int row = f >> 5;
                int s0  = f & 31;
                cp_async16(&en[row * RPAD + s0],
                           &eq[(size_t)((ch + 1) * 64 + row) * 32 + s0]);
            }
        }
        cp_async_commit();

        // ---- 256 x 64 x 128d GEMM, f32x2-packed accumulators ----
        unsigned long long acc[4][8];
        #pragma unroll
        for (int a = 0; a < 4; a++)
            #pragma unroll
            for (int b2 = 0; b2 < 8; b2++) acc[a][b2] = 0ULL;

        for (int d4 = 0; d4 < 32; ++d4) {
            float4 ev[8];
            #pragma unroll
            for (int jc = 0; jc < 8; jc++)
                ev[jc] = eb[(tx + 8 * jc) * RPAD + d4];
            #pragma unroll
            for (int jp = 0; jp < 4; jp++) {
                const float4 ra = r4s[(ty + 64 * jp) * RPAD + d4];
                const unsigned long long r01 = ((const unsigned long long*)&ra)[0];
                const unsigned long long r23 = ((const unsigned long long*)&ra)[1];
                #pragma unroll
                for (int jc = 0; jc < 8; jc++)
                    ffma2(acc[jp][jc], r01, ((const unsigned long long*)&ev[jc])[0]);
                #pragma unroll
                for (int jc = 0; jc < 8; jc++)
                    ffma2(acc[jp][jc], r23, ((const unsigned long long*)&ev[jc])[1]);
            }
        }

        // ---- epilogue: score = 2*(lo+hi) - |e|^2, running first-max argmax ----
        #pragma unroll
        for (int jc = 0; jc < 8; jc++) {
            const float cn = g_cnorm[q * K_ + ch * 64 + tx + 8 * jc];
            const int   cg = ch * 64 + tx + 8 * jc;
            #pragma unroll
            for (int jp = 0; jp < 4; jp++) {
                const unsigned long long a = acc[jp][jc];
                const float lo = __uint_as_float((unsigned)(a & 0xffffffffu));
                const float hi = __uint_as_float((unsigned)(a >> 32));
                const float s  = 2.0f * (lo + hi) - cn;
                if (s > best[jp]) { best[jp] = s; bidx[jp] = cg; }
            }
        }
    }

    // ---- reduce argmax across the 8 tx-lanes per point ----
    #pragma unroll
    for (int jp = 0; jp < 4; jp++) {
        float v  = best[jp];
        int   ix = bidx[jp];
        #pragma unroll
        for (int delta = 1; delta < 8; delta <<= 1) {
            float ov = __shfl_xor_sync(0xffffffffu, v, delta);
            int   oi = __shfl_xor_sync(0xffffffffu, ix, delta);
            if (ov > v || (ov == v && oi < ix)) { v = ov; ix = oi; }
        }
        if (tx == 0) sidx[ty + 64 * jp] = ix;
    }
    __syncthreads();

    // ---- write indices as float (output dtype = float32) ----
    if (tid < PTILE) {
        int n = blockStart + tid;
        if (n < N_) out[(size_t)q * N_ + n] = (float)sidx[tid];
    }

    // ---- residual update: r(smem) - e[best] -> global ----
    #pragma unroll
    for (int i = 0; i < 16; i++) {
        int f  = tid + 512 * i;
        int p  = f >> 5;
        int d4 = f & 31;
        int n  = blockStart + p;
        if (n < N_) {
            float4 r = r4s[p * RPAD + d4];
            float4 e = eq[(size_t)sidx[p] * 32 + d4];
            float4 w;
            w.x = r.x - e.x; w.y = r.y - e.y; w.z = r.z - e.z; w.w = r.w - e.w;
            rg[(size_t)n * 32 + d4] = w;
        }
    }
}

// ---------------------------------------------------------------------------
extern "C" void kernel_launch(void* const* d_in, const int* in_sizes, int n_in,
                              void* d_out, int out_size)
{
    const float* embeddings = (const float*)d_in[0];
    const float* embed      = (const float*)d_in[1];
    if (n_in >= 2 && in_sizes[0] == Q_ * K_ * D_ && in_sizes[1] == B_ * D_ * T_) {
        const float* t = embeddings; embeddings = embed; embed = t;
    }
    float* out = (float*)d_out;

    const int smem_bytes = (RT_F4 + 2 * ET_F4) * 16 + 1024;   // 203,776 B
    cudaFuncSetAttribute(rvq_layer_kernel,
                         cudaFuncAttributeMaxDynamicSharedMemorySize, smem_bytes);

    transpose_kernel<<<dim3(71, 4, 32), dim3(32, 8)>>>(embeddings);
    cnorm_kernel<<<4096, 256>>>(embed);
    for (int q = 0; q < Q_; q++) {
        rvq_layer_kernel<<<NBLK, 512, smem_bytes>>>(embed, q, out);
    }
}

// round 9
// speedup vs baseline: 1.0030x; 1.0030x over previous
#include <cuda_runtime.h>
#include <cstdint>

#define B_ 32
#define D_ 128
#define T_ 2250
#define Q_ 32
#define K_ 1024
#define N_ (B_*T_)          // 72000
#define NBLK 563            // ceil(N/128)

// Residual scratch [N][D] and per-code squared norms [Q][K].
__device__ __align__(16) float g_resid[(size_t)N_ * D_];
__device__ __align__(16) float g_cnorm[Q_ * K_];

// ---------------------------------------------------------------------------
__global__ void transpose_kernel(const float* __restrict__ in)
{
    __shared__ float tile[32][33];
    const int b  = blockIdx.z;
    const int t0 = blockIdx.x * 32;
    const int d0 = blockIdx.y * 32;
    const int tx = threadIdx.x;
    const int ty = threadIdx.y;

    #pragma unroll
    for (int k = 0; k < 4; k++) {
        int d = d0 + ty + k * 8;
        int t = t0 + tx;
        float v = 0.0f;
        if (t < T_) v = in[((size_t)b * D_ + d) * T_ + t];
        tile[ty + k * 8][tx] = v;
    }
    __syncthreads();
    #pragma unroll
    for (int k = 0; k < 4; k++) {
        int t = t0 + ty + k * 8;
        int d = d0 + tx;
        if (t < T_) g_resid[((size_t)b * T_ + t) * D_ + d] = tile[tx][ty + k * 8];
    }
}

// ---------------------------------------------------------------------------
__global__ void cnorm_kernel(const float* __restrict__ embed)
{
    const int wid  = threadIdx.x >> 5;
    const int lane = threadIdx.x & 31;
    const int code = blockIdx.x * 8 + wid;
    float s = 0.0f;
    #pragma unroll
    for (int j = 0; j < 4; j++) {
        float v = embed[(size_t)code * D_ + lane + 32 * j];
        s = fmaf(v, v, s);
    }
    #pragma unroll
    for (int d = 16; d; d >>= 1) s += __shfl_xor_sync(0xffffffffu, s, d);
    if (lane == 0) g_cnorm[code] = s;
}

// ---------------------------------------------------------------------------
// Packed dual-FMA: acc.(lo,hi) += a.(lo,hi) * b.(lo,hi)   (sm_100+ f32x2)
__device__ __forceinline__ void ffma2(unsigned long long& acc,
                                      unsigned long long a,
                                      unsigned long long b)
{
    asm("fma.rn.f32x2 %0, %1, %2, %0;" : "+l"(acc) : "l"(a), "l"(b));
}

// ---------------------------------------------------------------------------
// One RVQ layer. Block = 512 threads (tx = tid&15, ty = tid>>4), 128 points.
// K in 8 chunks of 128 codes, full D=128 resident in smem.
// Thread micro-tile: 4 points (p = ty + 32*jp) x 8 codes (c = tx + 16*jc).
// Inner loop jc-OUTER: one ev quad live at a time (small reg footprint so
// ptxas can unroll d4 and pipeline LDS ahead of the FFMA2 burst).
// Per-acc arithmetic order IDENTICAL to rounds 5-8:
//   for d4 = 0..31 ascending: acc += r01*e01 then acc += r23*e23.
// smem: r tile 128 x 33 float4 + e tile 128 x 33 float4 + sidx = 135.7 KB.
// ---------------------------------------------------------------------------
#define RPAD 33
#define RT_F4 (128 * RPAD)      // 4224 float4 per tile

__global__ void __launch_bounds__(512, 1)
rvq_layer_kernel(const float* __restrict__ embed_all, int q, float* __restrict__ out)
{
    extern __shared__ float4 sm4[];
    float4* r4s  = sm4;                       // 67,584 B
    float4* e4s  = sm4 + RT_F4;               // 67,584 B
    int*    sidx = (int*)(sm4 + 2 * RT_F4);   // 512 B

    const int tid = threadIdx.x;
    const int tx  = tid & 15;
    const int ty  = tid >> 4;                 // 0..31
    const int blockStart = blockIdx.x * 128;

    const float4* eq = (const float4*)(embed_all + (size_t)q * (K_ * D_));
    float4* rg = (float4*)g_resid;

    // ---- load residual tile: 128 pts x 32 float4 ----
    #pragma unroll
    for (int i = 0; i < 8; i++) {
        int f  = tid + 512 * i;
        int p  = f >> 5;
        int s0 = f & 31;
        int n  = blockStart + p;
        if (n >= N_) n = 0;
        r4s[p * RPAD + s0] = rg[(size_t)n * 32 + s0];
    }

    float best[4];
    int   bidx[4];
    #pragma unroll
    for (int j = 0; j < 4; j++) { best[j] = -3.4e38f; bidx[j] = 0; }

    for (int ch = 0; ch < 8; ++ch) {
        __syncthreads();   // previous chunk's readers done with e4s
        // ---- load e tile: 128 codes x 32 float4 ----
        #pragma unroll
        for (int i = 0; i < 8; i++) {
            int f   = tid + 512 * i;
            int row = f >> 5;
            int s0  = f & 31;
            e4s[row * RPAD + s0] = eq[(size_t)(ch * 128 + row) * 32 + s0];
        }
        __syncthreads();

        // ---- 128 x 128 x 128d GEMM, f32x2-packed accumulators ----
        unsigned long long acc[4][8];
        #pragma unroll
        for (int a = 0; a < 4; a++)
            #pragma unroll
            for (int b2 = 0; b2 < 8; b2++) acc[a][b2] = 0ULL;

        for (int d4 = 0; d4 < 32; ++d4) {
            unsigned long long r01[4], r23[4];
            #pragma unroll
            for (int jp = 0; jp < 4; jp++) {
                const float4 ra = r4s[(ty + 32 * jp) * RPAD + d4];
                r01[jp] = ((const unsigned long long*)&ra)[0];
                r23[jp] = ((const unsigned long long*)&ra)[1];
            }
            #pragma unroll
            for (int jc = 0; jc < 8; jc++) {
                const float4 ev = e4s[(tx + 16 * jc) * RPAD + d4];
                const unsigned long long e01 = ((const unsigned long long*)&ev)[0];
                const unsigned long long e23 = ((const unsigned long long*)&ev)[1];
                #pragma unroll
                for (int jp = 0; jp < 4; jp++) {
                    ffma2(acc[jp][jc], r01[jp], e01);
                    ffma2(acc[jp][jc], r23[jp], e23);
                }
            }
        }

        // ---- epilogue: score = 2*(lo+hi) - |e|^2, running first-max argmax ----
        #pragma unroll
        for (int jc = 0; jc < 8; jc++) {
            const float cn = g_cnorm[q * K_ + ch * 128 + tx + 16 * jc];
            const int   cg = ch * 128 + tx + 16 * jc;
            #pragma unroll
            for (int jp = 0; jp < 4; jp++) {
                const unsigned long long a = acc[jp][jc];
                const float lo = __uint_as_float((unsigned)(a & 0xffffffffu));
                const float hi = __uint_as_float((unsigned)(a >> 32));
                const float s  = 2.0f * (lo + hi) - cn;
                if (s > best[jp]) { best[jp] = s; bidx[jp] = cg; }
            }
        }
    }

    // ---- reduce argmax across the 16 tx-lanes (half-warp) per point ----
    #pragma unroll
    for (int jp = 0; jp < 4; jp++) {
        float v  = best[jp];
        int   ix = bidx[jp];
        #pragma unroll
        for (int delta = 1; delta < 16; delta <<= 1) {
            float ov = __shfl_xor_sync(0xffffffffu, v, delta);
            int   oi = __shfl_xor_sync(0xffffffffu, ix, delta);
            if (ov > v || (ov == v && oi < ix)) { v = ov; ix = oi; }
        }
        if (tx == 0) sidx[ty + 32 * jp] = ix;
    }
    __syncthreads();

    // ---- write indices as float (output dtype = float32) ----
    if (tid < 128) {
        int n = blockStart + tid;
        if (n < N_) out[(size_t)q * N_ + n] = (float)sidx[tid];
    }

    // ---- residual update: r(smem) - e[best] -> global ----
    #pragma unroll
    for (int i = 0; i < 8; i++) {
        int f  = tid + 512 * i;
        int p  = f >> 5;
        int d4 = f & 31;
        int n  = blockStart + p;
        if (n < N_) {
            float4 r = r4s[p * RPAD + d4];
            float4 e = eq[(size_t)sidx[p] * 32 + d4];
            float4 w;
            w.x = r.x - e.x; w.y = r.y - e.y; w.z = r.z - e.z; w.w = r.w - e.w;
            rg[(size_t)n * 32 + d4] = w;
        }
    }
}

// ---------------------------------------------------------------------------
extern "C" void kernel_launch(void* const* d_in, const int* in_sizes, int n_in,
                              void* d_out, int out_size)
{
    const float* embeddings = (const float*)d_in[0];
    const float* embed      = (const float*)d_in[1];
    if (n_in >= 2 && in_sizes[0] == Q_ * K_ * D_ && in_sizes[1] == B_ * D_ * T_) {
        const float* t = embeddings; embeddings = embed; embed = t;
    }
    float* out = (float*)d_out;

    const int smem_bytes = 2 * RT_F4 * 16 + 512;   // 135,680 B
    cudaFuncSetAttribute(rvq_layer_kernel,
                         cudaFuncAttributeMaxDynamicSharedMemorySize, smem_bytes);

    transpose_kernel<<<dim3(71, 4, 32), dim3(32, 8)>>>(embeddings);
    cnorm_kernel<<<4096, 256>>>(embed);
    for (int q = 0; q < Q_; q++) {
        rvq_layer_kernel<<<NBLK, 512, smem_bytes>>>(embed, q, out);
    }
}